// round 13
// baseline (speedup 1.0000x reference)
#include <cuda_runtime.h>
#include <cuda_bf16.h>
#include <cstdint>

// ---------------------------------------------------------------- problem
#define NROWS    32768
#define DIM      64
#define KCODES   1024
#define MTILE    128             // rows per CTA
#define NC       64              // codes per chunk
#define NCHUNK   (KCODES / NC)   // 16
#define NCTAS    (NROWS / MTILE) // 256
#define TPB      256             // 8 warps, 16 rows each
#define TAU      2e-3f           // covers worst-case 1-pass bf16 error (5.4e-4) x2 + ties
#define CAP      8               // per-lane (covers a 512-code subset)

// Output layout (flattened fp32): [quantized_st | vq_loss | indices | perplexity]
#define OFF_Q   0
#define OFF_L   2097152
#define OFF_I   2097153
#define OFF_P   2129921

// ---------------------------------------------------------------- smem layout
#define RSA 144                  // bf16 tile row stride (bytes): conflict-free frags
#define RSS 272                  // score tile row stride (bytes)

#define SM_AHI   0                           // z-hi tile: 128*144 = 18432
#define SM_B0    (MTILE * RSA)               // 18432; two B buffers of 64*144
#define BBUF     (NC * RSA)                  // 9216
#define SM_SC    (SM_B0 + 2 * BBUF)          // 36864 (+34816)
#define SM_ESQ   (SM_SC + MTILE * RSS)       // 71680 (+4096)
#define SM_TOTAL (SM_ESQ + KCODES * 4)       // 75776 (2 CTAs/SM)

// ---------------------------------------------------------------- scratch
__device__ __align__(16) __nv_bfloat16 g_zhi[NROWS * DIM];
__device__ __align__(16) __nv_bfloat16 g_ehi[KCODES * DIM];
__device__ float  g_esq[KCODES];
__device__ int    g_counts[KCODES];
__device__ double g_losssum;

// m16n8k16 bf16 MMA, fp32 accumulate (base sm_80+ PTX)
__device__ __forceinline__ void mma16816(float (&c)[4],
                                         uint32_t a0, uint32_t a1, uint32_t a2, uint32_t a3,
                                         uint32_t b0, uint32_t b1) {
    asm("mma.sync.aligned.m16n8k16.row.col.f32.bf16.bf16.f32 "
        "{%0,%1,%2,%3}, {%4,%5,%6,%7}, {%8,%9}, {%0,%1,%2,%3};"
        : "+f"(c[0]), "+f"(c[1]), "+f"(c[2]), "+f"(c[3])
        : "r"(a0), "r"(a1), "r"(a2), "r"(a3), "r"(b0), "r"(b1));
}
__device__ __forceinline__ uint32_t lds32(const char* p) {
    return *reinterpret_cast<const uint32_t*>(p);
}

// ---------------------------------------------------------------- prep kernels
__global__ void vq_prep_z(const float* __restrict__ z, int half) {
    int i = half * (NROWS * DIM / 2) + blockIdx.x * 256 + threadIdx.x;
    g_zhi[i] = __float2bfloat16(z[i]);
}

__global__ void vq_prep_cb(const float* __restrict__ codebook) {
    int i = blockIdx.x * 256 + threadIdx.x;   // 65536 threads
    g_ehi[i] = __float2bfloat16(codebook[i]);
    int wcode = i >> 5, lane = i & 31;
    if (wcode < KCODES) {
        const float2* e = reinterpret_cast<const float2*>(codebook + wcode * DIM);
        float2 t = e[lane];
        float s = fmaf(t.x, t.x, t.y * t.y);
        #pragma unroll
        for (int off = 16; off; off >>= 1)
            s += __shfl_xor_sync(0xffffffffu, s, off);
        if (lane == 0) g_esq[wcode] = s;
    }
    if (i < KCODES) g_counts[i] = 0;
    if (i == 0) g_losssum = 0.0;
}

// ---------------------------------------------------------------- main
__global__ __launch_bounds__(TPB, 2) void vq_main(
    const float* __restrict__ z,
    const float* __restrict__ codebook,
    float* __restrict__ out)
{
    extern __shared__ char smem[];
    const int tid  = threadIdx.x;
    const int wid  = tid >> 5;
    const int lane = tid & 31;
    const int g    = lane >> 2;     // groupID
    const int tg   = lane & 3;      // threadID in group
    const int row0 = blockIdx.x * MTILE;

    float* sesq = reinterpret_cast<float*>(smem + SM_ESQ);

    // ---- stage A (z-hi, 128 rows) + esq; stage B chunk 0 into buf0
    {
        const uint4* shi = reinterpret_cast<const uint4*>(g_zhi + (size_t)row0 * DIM);
        #pragma unroll
        for (int i = tid; i < MTILE * 8; i += TPB) {
            int rw = i >> 3, kc = i & 7;
            *reinterpret_cast<uint4*>(smem + SM_AHI + rw * RSA + kc * 16) = shi[i];
        }
        const uint4* bhi = reinterpret_cast<const uint4*>(g_ehi);
        #pragma unroll
        for (int i = tid; i < NC * 8; i += TPB) {
            int rw = i >> 3, kc = i & 7;
            *reinterpret_cast<uint4*>(smem + SM_B0 + rw * RSA + kc * 16) = bhi[i];
        }
        #pragma unroll
        for (int i = tid; i < KCODES; i += TPB) sesq[i] = g_esq[i];
    }
    __syncthreads();

    // per-lane candidate state (lane pair shares a row; half = lane&1)
    const int lrow = 16 * wid + (lane >> 1);   // local row this lane scans
    const int half = lane & 1;
    float smin = 3.402823466e38f;
    int   ncand = 0;
    bool  ovf = false;
    int   ck[CAP];
    float cs[CAP];

#define TRY_INSERT(kk, ss) do {                                               \
    if ((ss) <= smin + TAU) {                                                 \
        if (ncand < CAP) { ck[ncand] = (kk); cs[ncand] = (ss); ++ncand; }     \
        else {                                                                 \
            int m_ = 0;                                                        \
            for (int ii = 0; ii < CAP; ++ii)                                   \
                if (cs[ii] <= smin + TAU) { ck[m_] = ck[ii]; cs[m_] = cs[ii]; ++m_; } \
            ncand = m_;                                                        \
            if (ncand < CAP) { ck[ncand] = (kk); cs[ncand] = (ss); ++ncand; }  \
            else ovf = true;                                                   \
        }                                                                      \
    } } while (0)

    for (int c = 0; c < NCHUNK; ++c) {
        // ---- prefetch chunk c+1 into registers (latency overlapped)
        uint4 ph0, ph1;
        if (c + 1 < NCHUNK) {
            const uint4* bhi = reinterpret_cast<const uint4*>(g_ehi + (size_t)(c + 1) * NC * DIM);
            ph0 = bhi[tid]; ph1 = bhi[tid + TPB];
        }

        const char* BHI = smem + SM_B0 + (c & 1) * BBUF;

        // ---- single-pass MMA: acc = zhi * ehi (fp32 accum)
        float acc[8][4];
        #pragma unroll
        for (int j = 0; j < 8; ++j)
            #pragma unroll
            for (int q = 0; q < 4; ++q) acc[j][q] = 0.f;

        #pragma unroll
        for (int t = 0; t < 4; ++t) {
            // k-step t spans bytes [32t, 32t+32) of the 128-byte bf16 row
            const uint32_t aoff = (uint32_t)(16 * wid + g) * RSA + 32 * t + 4 * tg;
            uint32_t ah[4];
            ah[0] = lds32(smem + SM_AHI + aoff);
            ah[1] = lds32(smem + SM_AHI + aoff + 8 * RSA);
            ah[2] = lds32(smem + SM_AHI + aoff + 16);
            ah[3] = lds32(smem + SM_AHI + aoff + 8 * RSA + 16);

            #pragma unroll
            for (int jb = 0; jb < 2; ++jb) {
                uint32_t bh[4][2];
                #pragma unroll
                for (int jj = 0; jj < 4; ++jj) {
                    uint32_t boff = (uint32_t)(8 * (4 * jb + jj) + g) * RSA + 32 * t + 4 * tg;
                    bh[jj][0] = lds32(BHI + boff);
                    bh[jj][1] = lds32(BHI + boff + 16);
                }
                // dependent MMAs on the same acc are 4 apart
                #pragma unroll
                for (int jj = 0; jj < 4; ++jj)
                    mma16816(acc[4 * jb + jj], ah[0], ah[1], ah[2], ah[3], bh[jj][0], bh[jj][1]);
            }
        }

        // ---- transpose with esq fused: write final scores s = esq - 2m
        const int kb = c * NC;
        #pragma unroll
        for (int j = 0; j < 8; ++j) {
            float2 eq = *reinterpret_cast<const float2*>(sesq + kb + 8 * j + 2 * tg);
            float s0 = __fmaf_rn(-2.f, acc[j][0], eq.x);
            float s1 = __fmaf_rn(-2.f, acc[j][1], eq.y);
            float s2 = __fmaf_rn(-2.f, acc[j][2], eq.x);
            float s3 = __fmaf_rn(-2.f, acc[j][3], eq.y);
            uint32_t r0 = (uint32_t)(16 * wid + g);
            uint32_t coff = (uint32_t)(8 * j + 2 * tg) * 4;
            *reinterpret_cast<float2*>(smem + SM_SC + r0 * RSS + coff) = make_float2(s0, s1);
            *reinterpret_cast<float2*>(smem + SM_SC + (r0 + 8) * RSS + coff) = make_float2(s2, s3);
        }
        __syncwarp();

        // ---- scan half-row: 32 codes (pass 1 chunk-min, pass 2 insert)
        {
            const float4* srow = reinterpret_cast<const float4*>(
                smem + SM_SC + (uint32_t)lrow * RSS + half * 128);
            float cmin = 3.402823466e38f;
            #pragma unroll
            for (int q = 0; q < 8; ++q) {
                float4 s4 = srow[q];
                cmin = fminf(cmin, fminf(fminf(s4.x, s4.y), fminf(s4.z, s4.w)));
            }
            smin = fminf(smin, cmin);
            int k0 = kb + half * 32;
            #pragma unroll
            for (int q = 0; q < 8; ++q) {
                float4 s4 = srow[q];
                TRY_INSERT(k0 + 4 * q + 0, s4.x);
                TRY_INSERT(k0 + 4 * q + 1, s4.y);
                TRY_INSERT(k0 + 4 * q + 2, s4.z);
                TRY_INSERT(k0 + 4 * q + 3, s4.w);
            }
        }

        // ---- store prefetched chunk into the other buffer, then one sync
        if (c + 1 < NCHUNK) {
            char* DHI = smem + SM_B0 + ((c + 1) & 1) * BBUF;
            int i0 = tid, i1 = tid + TPB;
            *reinterpret_cast<uint4*>(DHI + (i0 >> 3) * RSA + (i0 & 7) * 16) = ph0;
            *reinterpret_cast<uint4*>(DHI + (i1 >> 3) * RSA + (i1 & 7) * 16) = ph1;
        }
        __syncthreads();
    }

    // ---------------- exact refinement (reference fp32 rounding, R1/R2-proven)
    const int r = row0 + lrow;
    float zq[DIM];
    {
        const float4* zr = reinterpret_cast<const float4*>(z + (size_t)r * DIM);
        #pragma unroll
        for (int i = 0; i < DIM / 4; ++i) {
            float4 t = zr[i];
            zq[4 * i] = t.x; zq[4 * i + 1] = t.y; zq[4 * i + 2] = t.z; zq[4 * i + 3] = t.w;
        }
    }
    float zsq = 0.f;
    #pragma unroll
    for (int i = 0; i < DIM; ++i) zsq = fmaf(zq[i], zq[i], zsq);

    float best = 3.402823466e38f;
    int   bestk = KCODES;
    if (!ovf) {
        for (int i = 0; i < ncand; ++i) {
            if (cs[i] > smin + TAU) continue;
            int k = ck[i];
            const float* e = codebook + (size_t)k * DIM;
            float m = 0.f;
            #pragma unroll
            for (int d = 0; d < DIM; ++d) m = fmaf(zq[d], e[d], m);
            float dd = __fmaf_rn(-2.f, m, zsq + sesq[k]);
            if (dd < best || (dd == best && k < bestk)) { best = dd; bestk = k; }
        }
    } else {
        // exact scan over this lane's own 512-code subset
        for (int blk = 0; blk < NCHUNK; ++blk) {
            int kb2 = blk * NC + half * 32;
            for (int kk = 0; kk < 32; ++kk) {
                int k = kb2 + kk;
                const float* e = codebook + (size_t)k * DIM;
                float m = 0.f;
                #pragma unroll
                for (int d = 0; d < DIM; ++d) m = fmaf(zq[d], e[d], m);
                float dd = __fmaf_rn(-2.f, m, zsq + sesq[k]);
                if (dd < best || (dd == best && k < bestk)) { best = dd; bestk = k; }
            }
        }
    }

    // merge lane pair: smaller exact d, tie -> smaller k (jnp first-min rule)
    {
        float ob = __shfl_xor_sync(0xffffffffu, best, 1);
        int   ok = __shfl_xor_sync(0xffffffffu, bestk, 1);
        if (ob < best || (ob == best && ok < bestk)) { best = ob; bestk = ok; }
    }

    // ---------------- outputs: stage quantized row halves into SC, loss partials
    float lsum = 0.f;
    {
        const float* eb = codebook + (size_t)bestk * DIM + half * 32;
        const float* zh = zq + half * 32;
        float* qrow = reinterpret_cast<float*>(smem + SM_SC + (uint32_t)lrow * RSS) + half * 32;
        #pragma unroll
        for (int i = 0; i < 8; ++i) {
            float d0 = eb[4 * i + 0] - zh[4 * i + 0];
            float d1 = eb[4 * i + 1] - zh[4 * i + 1];
            float d2 = eb[4 * i + 2] - zh[4 * i + 2];
            float d3 = eb[4 * i + 3] - zh[4 * i + 3];
            float4 qv = make_float4(zh[4 * i + 0] + d0, zh[4 * i + 1] + d1,
                                    zh[4 * i + 2] + d2, zh[4 * i + 3] + d3);
            *reinterpret_cast<float4*>(qrow + 4 * i) = qv;
            lsum = fmaf(d0, d0, lsum); lsum = fmaf(d1, d1, lsum);
            lsum = fmaf(d2, d2, lsum); lsum = fmaf(d3, d3, lsum);
        }
        if (half == 0) {
            out[OFF_I + r] = (float)bestk;
            atomicAdd(&g_counts[bestk], 1);   // spread-address REDG
        }
    }
    #pragma unroll
    for (int off = 16; off; off >>= 1)
        lsum += __shfl_down_sync(0xffffffffu, lsum, off);
    if (lane == 0) atomicAdd(&g_losssum, (double)lsum);

    // coalesced copy of quantized tile SC -> gmem
    __syncthreads();
    float* oq = out + OFF_Q + (size_t)row0 * DIM;
    #pragma unroll
    for (int i = tid; i < MTILE * (DIM / 4); i += TPB) {
        int rw = i >> 4, q = i & 15;
        float4 v = *reinterpret_cast<const float4*>(smem + SM_SC + (uint32_t)rw * RSS + q * 16);
        reinterpret_cast<float4*>(oq + (size_t)rw * DIM)[q] = v;
    }
}

// ---------------------------------------------------------------- finalize
__global__ void vq_final(float* __restrict__ out) {
    __shared__ double red[32];
    int t = threadIdx.x;  // 1024 threads
    float c = (float)g_counts[t];
    float p = c * (1.0f / 32768.0f);
    float term = p * logf(p + 1e-10f);
    double v = (double)term;
    #pragma unroll
    for (int off = 16; off; off >>= 1)
        v += __shfl_down_sync(0xffffffffu, v, off);
    if ((t & 31) == 0) red[t >> 5] = v;
    __syncthreads();
    if (t < 32) {
        double w = red[t];
        #pragma unroll
        for (int off = 16; off; off >>= 1)
            w += __shfl_down_sync(0xffffffffu, w, off);
        if (t == 0) {
            float s = (float)w;
            out[OFF_P] = expf(-s);
            float m = (float)(g_losssum * (1.0 / 2097152.0));
            out[OFF_L] = m + 0.25f * m;
        }
    }
}

// ---------------------------------------------------------------- launch
extern "C" void kernel_launch(void* const* d_in, const int* in_sizes, int n_in,
                              void* d_out, int out_size) {
    const float* z        = (const float*)d_in[0];
    const float* codebook = (const float*)d_in[1];
    float* out = (float*)d_out;

    cudaFuncSetAttribute(vq_main, cudaFuncAttributeMaxDynamicSharedMemorySize, SM_TOTAL);

    vq_prep_z<<<4096, 256>>>(z, 0);                       // idx 0
    vq_prep_z<<<4096, 256>>>(z, 1);                       // idx 1
    vq_prep_cb<<<256, 256>>>(codebook);                   // idx 2
    vq_main<<<NCTAS, TPB, SM_TOTAL>>>(z, codebook, out);  // idx 3 (ncu slot)
    vq_final<<<1, KCODES>>>(out);                         // idx 4
}

// round 14
// speedup vs baseline: 4.1336x; 4.1336x over previous
#include <cuda_runtime.h>
#include <cuda_bf16.h>
#include <cstdint>

// ---------------------------------------------------------------- problem
#define NROWS    32768
#define DIM      64
#define KCODES   1024
#define MTILE    128             // rows per CTA
#define NC       64              // codes per chunk
#define NCHUNK   (KCODES / NC)   // 16
#define NCTAS    (NROWS / MTILE) // 256
#define TPB      256             // 8 warps, 16 rows each
#define TAU      5e-4f           // covers dropped z*e_lo (2e-4 worst) + tie window
#define CAP      8               // per-lane (covers a 512-code subset)

// Output layout (flattened fp32): [quantized_st | vq_loss | indices | perplexity]
#define OFF_Q   0
#define OFF_L   2097152
#define OFF_I   2097153
#define OFF_P   2129921

// ---------------------------------------------------------------- smem layout
#define RSA 144                  // bf16 tile row stride (bytes): conflict-free frags
#define RSS 272                  // score tile row stride (bytes)

#define SM_AHI   0
#define SM_ALO   (SM_AHI + MTILE * RSA)      // 18432
#define SM_B0    (SM_ALO + MTILE * RSA)      // 36864; two e_hi buffers
#define BBUF     (NC * RSA)                  // 9216
#define SM_SC    (SM_B0 + 2 * BBUF)          // 55296 (+34816)
#define SM_ESQ   (SM_SC + MTILE * RSS)       // 90112 (+4096)
#define SM_TOTAL (SM_ESQ + KCODES * 4)       // 94208 (2 CTAs/SM)

// ---------------------------------------------------------------- scratch
__device__ __align__(16) __nv_bfloat16 g_zhi[NROWS * DIM];
__device__ __align__(16) __nv_bfloat16 g_zlo[NROWS * DIM];
__device__ __align__(16) __nv_bfloat16 g_ehi[KCODES * DIM];
__device__ float  g_esq[KCODES];
__device__ int    g_counts[KCODES];
__device__ double g_losssum;

// m16n8k16 bf16 MMA, fp32 accumulate (base sm_80+ PTX)
__device__ __forceinline__ void mma16816(float (&c)[4],
                                         uint32_t a0, uint32_t a1, uint32_t a2, uint32_t a3,
                                         uint32_t b0, uint32_t b1) {
    asm("mma.sync.aligned.m16n8k16.row.col.f32.bf16.bf16.f32 "
        "{%0,%1,%2,%3}, {%4,%5,%6,%7}, {%8,%9}, {%0,%1,%2,%3};"
        : "+f"(c[0]), "+f"(c[1]), "+f"(c[2]), "+f"(c[3])
        : "r"(a0), "r"(a1), "r"(a2), "r"(a3), "r"(b0), "r"(b1));
}
__device__ __forceinline__ uint32_t lds32(const char* p) {
    return *reinterpret_cast<const uint32_t*>(p);
}

// ---------------------------------------------------------------- prep kernels
__global__ void vq_prep_z(const float* __restrict__ z, int half) {
    int i = half * (NROWS * DIM / 2) + blockIdx.x * 256 + threadIdx.x;
    float v = z[i];
    __nv_bfloat16 h = __float2bfloat16(v);
    g_zhi[i] = h;
    g_zlo[i] = __float2bfloat16(v - __bfloat162float(h));
}

__global__ void vq_prep_cb(const float* __restrict__ codebook) {
    int i = blockIdx.x * 256 + threadIdx.x;   // 65536 threads
    g_ehi[i] = __float2bfloat16(codebook[i]);
    int wcode = i >> 5, lane = i & 31;
    if (wcode < KCODES) {
        const float2* e = reinterpret_cast<const float2*>(codebook + wcode * DIM);
        float2 t = e[lane];
        float s = fmaf(t.x, t.x, t.y * t.y);
        #pragma unroll
        for (int off = 16; off; off >>= 1)
            s += __shfl_xor_sync(0xffffffffu, s, off);
        if (lane == 0) g_esq[wcode] = s;
    }
    if (i < KCODES) g_counts[i] = 0;
    if (i == 0) g_losssum = 0.0;
}

// ---------------------------------------------------------------- main
__global__ __launch_bounds__(TPB, 2) void vq_main(
    const float* __restrict__ z,
    const float* __restrict__ codebook,
    float* __restrict__ out)
{
    extern __shared__ char smem[];
    const int tid  = threadIdx.x;
    const int wid  = tid >> 5;
    const int lane = tid & 31;
    const int g    = lane >> 2;     // groupID
    const int tg   = lane & 3;      // threadID in group
    const int row0 = blockIdx.x * MTILE;

    float* sesq = reinterpret_cast<float*>(smem + SM_ESQ);

    // ---- stage A (z hi/lo, 128 rows) + esq; stage B chunk 0 (e_hi) into buf0
    {
        const uint4* shi = reinterpret_cast<const uint4*>(g_zhi + (size_t)row0 * DIM);
        const uint4* slo = reinterpret_cast<const uint4*>(g_zlo + (size_t)row0 * DIM);
        #pragma unroll
        for (int i = tid; i < MTILE * 8; i += TPB) {
            int rw = i >> 3, kc = i & 7;
            *reinterpret_cast<uint4*>(smem + SM_AHI + rw * RSA + kc * 16) = shi[i];
            *reinterpret_cast<uint4*>(smem + SM_ALO + rw * RSA + kc * 16) = slo[i];
        }
        const uint4* bhi = reinterpret_cast<const uint4*>(g_ehi);
        #pragma unroll
        for (int i = tid; i < NC * 8; i += TPB) {
            int rw = i >> 3, kc = i & 7;
            *reinterpret_cast<uint4*>(smem + SM_B0 + rw * RSA + kc * 16) = bhi[i];
        }
        #pragma unroll
        for (int i = tid; i < KCODES; i += TPB) sesq[i] = g_esq[i];
    }
    __syncthreads();

    // per-lane candidate state (lane pair shares a row; half = lane&1)
    const int lrow = 16 * wid + (lane >> 1);   // local row this lane scans
    const int half = lane & 1;
    float smin = 3.402823466e38f;
    int   ncand = 0;
    bool  ovf = false;
    int   ck[CAP];
    float cs[CAP];

#define TRY_INSERT(kk, ss) do {                                               \
    if ((ss) <= smin + TAU) {                                                 \
        if (ncand < CAP) { ck[ncand] = (kk); cs[ncand] = (ss); ++ncand; }     \
        else {                                                                 \
            int m_ = 0;                                                        \
            for (int ii = 0; ii < CAP; ++ii)                                   \
                if (cs[ii] <= smin + TAU) { ck[m_] = ck[ii]; cs[m_] = cs[ii]; ++m_; } \
            ncand = m_;                                                        \
            if (ncand < CAP) { ck[ncand] = (kk); cs[ncand] = (ss); ++ncand; }  \
            else ovf = true;                                                   \
        }                                                                      \
    } } while (0)

    for (int c = 0; c < NCHUNK; ++c) {
        // ---- prefetch chunk c+1 (e_hi only) into registers
        uint4 ph0, ph1;
        if (c + 1 < NCHUNK) {
            const uint4* bhi = reinterpret_cast<const uint4*>(g_ehi + (size_t)(c + 1) * NC * DIM);
            ph0 = bhi[tid]; ph1 = bhi[tid + TPB];
        }

        const char* BHI = smem + SM_B0 + (c & 1) * BBUF;

        // ---- 2-pass MMA: acc = zhi*ehi + zlo*ehi (fp32 accum)
        float acc[8][4];
        #pragma unroll
        for (int j = 0; j < 8; ++j)
            #pragma unroll
            for (int q = 0; q < 4; ++q) acc[j][q] = 0.f;

        #pragma unroll
        for (int t = 0; t < 4; ++t) {
            // k-step t spans bytes [32t, 32t+32) of the 128-byte bf16 row
            const uint32_t aoff = (uint32_t)(16 * wid + g) * RSA + 32 * t + 4 * tg;
            uint32_t ah[4], al[4];
            ah[0] = lds32(smem + SM_AHI + aoff);
            ah[1] = lds32(smem + SM_AHI + aoff + 8 * RSA);
            ah[2] = lds32(smem + SM_AHI + aoff + 16);
            ah[3] = lds32(smem + SM_AHI + aoff + 8 * RSA + 16);
            al[0] = lds32(smem + SM_ALO + aoff);
            al[1] = lds32(smem + SM_ALO + aoff + 8 * RSA);
            al[2] = lds32(smem + SM_ALO + aoff + 16);
            al[3] = lds32(smem + SM_ALO + aoff + 8 * RSA + 16);

            #pragma unroll
            for (int jb = 0; jb < 2; ++jb) {
                uint32_t bh[4][2];
                #pragma unroll
                for (int jj = 0; jj < 4; ++jj) {
                    uint32_t boff = (uint32_t)(8 * (4 * jb + jj) + g) * RSA + 32 * t + 4 * tg;
                    bh[jj][0] = lds32(BHI + boff);
                    bh[jj][1] = lds32(BHI + boff + 16);
                }
                // pass-major: dependent MMAs on same acc are 4 apart
                #pragma unroll
                for (int jj = 0; jj < 4; ++jj)
                    mma16816(acc[4 * jb + jj], ah[0], ah[1], ah[2], ah[3], bh[jj][0], bh[jj][1]);
                #pragma unroll
                for (int jj = 0; jj < 4; ++jj)
                    mma16816(acc[4 * jb + jj], al[0], al[1], al[2], al[3], bh[jj][0], bh[jj][1]);
            }
        }

        // ---- transpose scores via smem (warp-local rows 16*wid..16*wid+15)
        #pragma unroll
        for (int j = 0; j < 8; ++j) {
            uint32_t r0 = (uint32_t)(16 * wid + g);
            uint32_t coff = (uint32_t)(8 * j + 2 * tg) * 4;
            *reinterpret_cast<float2*>(smem + SM_SC + r0 * RSS + coff) =
                make_float2(acc[j][0], acc[j][1]);
            *reinterpret_cast<float2*>(smem + SM_SC + (r0 + 8) * RSS + coff) =
                make_float2(acc[j][2], acc[j][3]);
        }
        __syncwarp();

        // ---- scan half-row: 32 codes (pass 1 chunk-min, pass 2 insert)
        {
            const float4* srow = reinterpret_cast<const float4*>(
                smem + SM_SC + (uint32_t)lrow * RSS + half * 128);
            const float4* erow = reinterpret_cast<const float4*>(sesq + c * NC + half * 32);
            float cmin = 3.402823466e38f;
            #pragma unroll
            for (int q = 0; q < 8; ++q) {
                float4 m4 = srow[q]; float4 e4 = erow[q];
                cmin = fminf(cmin, fmaf(-2.f, m4.x, e4.x));
                cmin = fminf(cmin, fmaf(-2.f, m4.y, e4.y));
                cmin = fminf(cmin, fmaf(-2.f, m4.z, e4.z));
                cmin = fminf(cmin, fmaf(-2.f, m4.w, e4.w));
            }
            smin = fminf(smin, cmin);
            int k0 = c * NC + half * 32;
            #pragma unroll
            for (int q = 0; q < 8; ++q) {
                float4 m4 = srow[q]; float4 e4 = erow[q];
                float s;
                s = fmaf(-2.f, m4.x, e4.x); TRY_INSERT(k0 + 4 * q + 0, s);
                s = fmaf(-2.f, m4.y, e4.y); TRY_INSERT(k0 + 4 * q + 1, s);
                s = fmaf(-2.f, m4.z, e4.z); TRY_INSERT(k0 + 4 * q + 2, s);
                s = fmaf(-2.f, m4.w, e4.w); TRY_INSERT(k0 + 4 * q + 3, s);
            }
        }

        // ---- store prefetched chunk into the other buffer, then one sync
        if (c + 1 < NCHUNK) {
            char* DHI = smem + SM_B0 + ((c + 1) & 1) * BBUF;
            int i0 = tid, i1 = tid + TPB;
            *reinterpret_cast<uint4*>(DHI + (i0 >> 3) * RSA + (i0 & 7) * 16) = ph0;
            *reinterpret_cast<uint4*>(DHI + (i1 >> 3) * RSA + (i1 & 7) * 16) = ph1;
        }
        __syncthreads();
    }

    // ---------------- exact refinement (reference fp32 rounding, R1/R2-proven)
    const int r = row0 + lrow;
    float zq[DIM];
    {
        const float4* zr = reinterpret_cast<const float4*>(z + (size_t)r * DIM);
        #pragma unroll
        for (int i = 0; i < DIM / 4; ++i) {
            float4 t = zr[i];
            zq[4 * i] = t.x; zq[4 * i + 1] = t.y; zq[4 * i + 2] = t.z; zq[4 * i + 3] = t.w;
        }
    }
    float zsq = 0.f;
    #pragma unroll
    for (int i = 0; i < DIM; ++i) zsq = fmaf(zq[i], zq[i], zsq);

    float best = 3.402823466e38f;
    int   bestk = KCODES;
    if (!ovf) {
        for (int i = 0; i < ncand; ++i) {
            if (cs[i] > smin + TAU) continue;
            int k = ck[i];
            const float* e = codebook + (size_t)k * DIM;
            float m = 0.f;
            #pragma unroll
            for (int d = 0; d < DIM; ++d) m = fmaf(zq[d], e[d], m);
            float dd = __fmaf_rn(-2.f, m, zsq + sesq[k]);
            if (dd < best || (dd == best && k < bestk)) { best = dd; bestk = k; }
        }
    } else {
        // exact scan over this lane's own 512-code subset
        for (int blk = 0; blk < NCHUNK; ++blk) {
            int kb2 = blk * NC + half * 32;
            for (int kk = 0; kk < 32; ++kk) {
                int k = kb2 + kk;
                const float* e = codebook + (size_t)k * DIM;
                float m = 0.f;
                #pragma unroll
                for (int d = 0; d < DIM; ++d) m = fmaf(zq[d], e[d], m);
                float dd = __fmaf_rn(-2.f, m, zsq + sesq[k]);
                if (dd < best || (dd == best && k < bestk)) { best = dd; bestk = k; }
            }
        }
    }

    // merge lane pair: smaller exact d, tie -> smaller k (jnp first-min rule)
    {
        float ob = __shfl_xor_sync(0xffffffffu, best, 1);
        int   ok = __shfl_xor_sync(0xffffffffu, bestk, 1);
        if (ob < best || (ob == best && ok < bestk)) { best = ob; bestk = ok; }
    }

    // ---------------- outputs: stage quantized row halves into SC, loss partials
    float lsum = 0.f;
    {
        const float* eb = codebook + (size_t)bestk * DIM + half * 32;
        const float* zh = zq + half * 32;
        float* qrow = reinterpret_cast<float*>(smem + SM_SC + (uint32_t)lrow * RSS) + half * 32;
        #pragma unroll
        for (int i = 0; i < 8; ++i) {
            float d0 = eb[4 * i + 0] - zh[4 * i + 0];
            float d1 = eb[4 * i + 1] - zh[4 * i + 1];
            float d2 = eb[4 * i + 2] - zh[4 * i + 2];
            float d3 = eb[4 * i + 3] - zh[4 * i + 3];
            float4 qv = make_float4(zh[4 * i + 0] + d0, zh[4 * i + 1] + d1,
                                    zh[4 * i + 2] + d2, zh[4 * i + 3] + d3);
            *reinterpret_cast<float4*>(qrow + 4 * i) = qv;
            lsum = fmaf(d0, d0, lsum); lsum = fmaf(d1, d1, lsum);
            lsum = fmaf(d2, d2, lsum); lsum = fmaf(d3, d3, lsum);
        }
        if (half == 0) {
            out[OFF_I + r] = (float)bestk;
            atomicAdd(&g_counts[bestk], 1);   // spread-address REDG
        }
    }
    #pragma unroll
    for (int off = 16; off; off >>= 1)
        lsum += __shfl_down_sync(0xffffffffu, lsum, off);
    if (lane == 0) atomicAdd(&g_losssum, (double)lsum);

    // coalesced copy of quantized tile SC -> gmem
    __syncthreads();
    float* oq = out + OFF_Q + (size_t)row0 * DIM;
    #pragma unroll
    for (int i = tid; i < MTILE * (DIM / 4); i += TPB) {
        int rw = i >> 4, q = i & 15;
        float4 v = *reinterpret_cast<const float4*>(smem + SM_SC + (uint32_t)rw * RSS + q * 16);
        reinterpret_cast<float4*>(oq + (size_t)rw * DIM)[q] = v;
    }
}

// ---------------------------------------------------------------- finalize
__global__ void vq_final(float* __restrict__ out) {
    __shared__ double red[32];
    int t = threadIdx.x;  // 1024 threads
    float c = (float)g_counts[t];
    float p = c * (1.0f / 32768.0f);
    float term = p * logf(p + 1e-10f);
    double v = (double)term;
    #pragma unroll
    for (int off = 16; off; off >>= 1)
        v += __shfl_down_sync(0xffffffffu, v, off);
    if ((t & 31) == 0) red[t >> 5] = v;
    __syncthreads();
    if (t < 32) {
        double w = red[t];
        #pragma unroll
        for (int off = 16; off; off >>= 1)
            w += __shfl_down_sync(0xffffffffu, w, off);
        if (t == 0) {
            float s = (float)w;
            out[OFF_P] = expf(-s);
            float m = (float)(g_losssum * (1.0 / 2097152.0));
            out[OFF_L] = m + 0.25f * m;
        }
    }
}

// ---------------------------------------------------------------- launch
extern "C" void kernel_launch(void* const* d_in, const int* in_sizes, int n_in,
                              void* d_out, int out_size) {
    const float* z        = (const float*)d_in[0];
    const float* codebook = (const float*)d_in[1];
    float* out = (float*)d_out;

    cudaFuncSetAttribute(vq_main, cudaFuncAttributeMaxDynamicSharedMemorySize, SM_TOTAL);

    vq_prep_z<<<4096, 256>>>(z, 0);                       // idx 0
    vq_prep_z<<<4096, 256>>>(z, 1);                       // idx 1
    vq_prep_cb<<<256, 256>>>(codebook);                   // idx 2
    vq_main<<<NCTAS, TPB, SM_TOTAL>>>(z, codebook, out);  // idx 3 (ncu slot)
    vq_final<<<1, KCODES>>>(out);                         // idx 4
}